// round 15
// baseline (speedup 1.0000x reference)
#include <cuda_runtime.h>

// QubitClassifier: 13-qubit ZZ-feature-map + variational circuit, B=512.
// One CTA per sample. State (8192 complex fp32) lives in shared memory.
// 256 threads x 32 amplitudes in registers; gates applied in 5-qubit
// register-blocked rounds (gates on distinct qubits commute).

#define NQ 13
#define QDIM 8192
#define PI_F 3.14159274101257324f   // float(pi), matches fp32 reference constant

// XOR swizzle so that per-round SMEM access is bank-conflict-free while
// register indices stay compile-time constant. Bijective on [0, 8192).
__device__ __forceinline__ int swz(int i) { return i ^ ((i >> 5) & 31); }

// Rz(b)Ry(a) gate: a0' = em*(ca*a0 - sa*a1), a1' = conj(em)*(sa*a0 + ca*a1)
// g = (ca, sa, em.x, em.y) with em = exp(-i b/2).
__device__ __forceinline__ void cgate(float2& a0, float2& a1, float4 g) {
    float ca = g.x, sa = g.y, ex = g.z, ey = g.w;
    float t0x = ca * a0.x - sa * a1.x;
    float t0y = ca * a0.y - sa * a1.y;
    float t1x = sa * a0.x + ca * a1.x;
    float t1y = sa * a0.y + ca * a1.y;
    a0.x = ex * t0x - ey * t0y;
    a0.y = ex * t0y + ey * t0x;
    a1.x = ex * t1x + ey * t1y;
    a1.y = ex * t1y - ey * t1x;
}

__device__ __forceinline__ void hpair(float2& a0, float2& a1) {
    float2 u = a0, v = a1;
    a0.x = u.x + v.x; a0.y = u.y + v.y;
    a1.x = u.x - v.x; a1.y = u.y - v.y;
}

// Global index for thread t, register slot m, per round map.
// MAP 0: register bits -> global bits 0..4  (qubits 12..8, strides 1..16)
// MAP 1: register bits -> global bits 5..9  (qubits 7..3)
// MAP 2: register bits 2..4 -> global bits 10..12 (qubits 2..0); bits 0..1 -> 8..9 (filler)
template <int MAP>
__device__ __forceinline__ int gidx(int t, int m) {
    if (MAP == 0) return (t << 5) | m;
    else if (MAP == 1) return ((t >> 5) << 10) | (m << 5) | (t & 31);
    else return ((m >> 2) << 10) | ((m & 3) << 8) | t;
}

template <int MAP>
__device__ __forceinline__ void load_amp(const float2* S, float2 amp[32], int t, bool ent) {
#pragma unroll
    for (int m = 0; m < 32; m++) {
        int idx = gidx<MAP>(t, m);
        float2 a = S[swz(idx)];
        if (ent && (__popc(idx & (idx >> 1)) & 1)) { a.x = -a.x; a.y = -a.y; }
        amp[m] = a;
    }
}

template <int MAP>
__device__ __forceinline__ void store_amp(float2* S, const float2 amp[32], int t) {
#pragma unroll
    for (int m = 0; m < 32; m++) S[swz(gidx<MAP>(t, m))] = amp[m];
}

template <int MAP>
__device__ __forceinline__ void apply_gates(float2 amp[32], const float4* GP, int l) {
    const int k0 = (MAP == 2) ? 2 : 0;
#pragma unroll
    for (int k = k0; k < 5; k++) {
        int q = (MAP == 0) ? (12 - k) : ((MAP == 1) ? (7 - k) : (4 - k));
        float4 g = GP[l * 13 + q];
#pragma unroll
        for (int j = 0; j < 32; j++)
            if (!((j >> k) & 1)) cgate(amp[j], amp[j | (1 << k)], g);
    }
}

template <int MAP>
__device__ __forceinline__ void apply_h(float2 amp[32]) {
    const int k0 = (MAP == 2) ? 2 : 0;
#pragma unroll
    for (int k = k0; k < 5; k++)
#pragma unroll
        for (int j = 0; j < 32; j++)
            if (!((j >> k) & 1)) hpair(amp[j], amp[j | (1 << k)]);
}

__global__ void __launch_bounds__(256, 1)
qubit_classifier_kernel(const float* __restrict__ x,
                        const float* __restrict__ theta,
                        const float* __restrict__ bias,
                        float* __restrict__ out)
{
    extern __shared__ char sm[];
    float2* S  = (float2*)sm;                                   // 65536 B: state
    float*  F  = (float*)(sm + 65536);                          // 32768 B: phi(b)
    float4* GP = (float4*)(sm + 65536 + 32768);                 //  1040 B: 65 gates
    float*  XS = (float*)(sm + 65536 + 32768 + 1040);           //    52 B
    float*  AS = XS + 13;                                       //    52 B
    float*  RED = AS + 13;                                      //    32 B

    const int t = threadIdx.x;
    const int b = blockIdx.x;

    // Gate parameters (shared across batch): th[l,q,0]=a, th[l,q,1]=b
    if (t < 65) {
        float tha = theta[2 * t], thb = theta[2 * t + 1];
        float sa, ca; sincosf(0.5f * tha, &sa, &ca);
        float sb, cb; sincosf(0.5f * thb, &sb, &cb);
        GP[t] = make_float4(ca, sa, cb, -sb);   // em = exp(-i thb/2)
    }
    if (t < 13) {
        float xv = x[b * 13 + t];
        XS[t] = xv;
        AS[t] = PI_F - xv;
    }
    __syncthreads();

    float Asum = 0.f;
#pragma unroll
    for (int q = 0; q < 13; q++) { float a = AS[q]; Asum += a * a; }

    // Split phi = u + 0.5*(v^2 - Asum): hi part from thread bits (global bits 5..12),
    // lo part from register bits (global bits 0..4). Bit p of idx <-> qubit 12-p.
    float uhi = 0.f, vhi = 0.f;
#pragma unroll
    for (int p = 5; p < 13; p++) {
        int bit = (t >> (p - 5)) & 1;
        float xv = XS[12 - p], av = AS[12 - p];
        uhi += bit ? -xv : xv;
        vhi += bit ? -av : av;
    }
    float xlo[5], alo[5];
#pragma unroll
    for (int k = 0; k < 5; k++) { xlo[k] = XS[12 - k]; alo[k] = AS[12 - k]; }

    float2 amp[32];

    // ---- Round 1 (MAP0): init amp = exp(i*phi)/8192 (both norm factors folded),
    //      store phi, apply H to qubits 12..8. ----
#pragma unroll
    for (int m = 0; m < 32; m++) {
        float u = uhi, v = vhi;
#pragma unroll
        for (int k = 0; k < 5; k++) {
            int bit = (m >> k) & 1;
            u += bit ? -xlo[k] : xlo[k];
            v += bit ? -alo[k] : alo[k];
        }
        float phi = u + 0.5f * (v * v - Asum);
        int idx = (t << 5) | m;
        F[swz(idx)] = phi;
        float sn, cs; sincosf(phi, &sn, &cs);
        const float c = 1.0f / 8192.0f;   // 2^{-13/2} (init) * 2^{-13/2} (FWHT norm)
        amp[m] = make_float2(cs * c, sn * c);
    }
    apply_h<0>(amp);
    store_amp<0>(S, amp, t);
    __syncthreads();

    // ---- Round 2 (MAP1): H on qubits 7..3 ----
    load_amp<1>(S, amp, t, false);
    apply_h<1>(amp);
    store_amp<1>(S, amp, t);
    __syncthreads();

    // ---- Round 3 (MAP2): H on qubits 2..0, then second d = exp(i*phi),
    //      then layer-0 gates for qubits 2..0 ----
    load_amp<2>(S, amp, t, false);
    apply_h<2>(amp);
#pragma unroll
    for (int m = 0; m < 32; m++) {
        int idx = gidx<2>(t, m);
        float phi = F[swz(idx)];
        float sn, cs; sincosf(phi, &sn, &cs);
        float2 a = amp[m];
        amp[m] = make_float2(a.x * cs - a.y * sn, a.x * sn + a.y * cs);
    }
    apply_gates<2>(amp, GP, 0);
    store_amp<2>(S, amp, t);
    __syncthreads();

    // ---- Rounds 4,5: layer-0 gates for qubits 12..8 and 7..3 ----
    load_amp<0>(S, amp, t, false);
    apply_gates<0>(amp, GP, 0);
    store_amp<0>(S, amp, t);
    __syncthreads();

    load_amp<1>(S, amp, t, false);
    apply_gates<1>(amp, GP, 0);
    store_amp<1>(S, amp, t);
    __syncthreads();

    // ---- Layers 1..4: ENT diagonal fused into first load; last round of
    //      layer 4 fuses parity-weighted probability reduction (no store). ----
    float acc = 0.f;
#pragma unroll 1
    for (int l = 1; l < 5; l++) {
        load_amp<0>(S, amp, t, true);           // * ENT = (-1)^popc(b & (b>>1))
        apply_gates<0>(amp, GP, l);
        store_amp<0>(S, amp, t);
        __syncthreads();

        load_amp<1>(S, amp, t, false);
        apply_gates<1>(amp, GP, l);
        store_amp<1>(S, amp, t);
        __syncthreads();

        load_amp<2>(S, amp, t, false);
        apply_gates<2>(amp, GP, l);
        if (l < 4) {
            store_amp<2>(S, amp, t);
            __syncthreads();
        } else {
#pragma unroll
            for (int m = 0; m < 32; m++) {
                int idx = gidx<2>(t, m);
                float p = amp[m].x * amp[m].x + amp[m].y * amp[m].y;
                acc += (__popc(idx) & 1) ? -p : p;
            }
        }
    }

    // Block reduction of acc
#pragma unroll
    for (int off = 16; off; off >>= 1)
        acc += __shfl_xor_sync(0xffffffffu, acc, off);
    if ((t & 31) == 0) RED[t >> 5] = acc;
    __syncthreads();
    if (t == 0) {
        float s = 0.f;
#pragma unroll
        for (int w = 0; w < 8; w++) s += RED[w];
        float logit = s + bias[0];
        out[2 * b + 0] = -logit;
        out[2 * b + 1] = logit;
    }
}

extern "C" void kernel_launch(void* const* d_in, const int* in_sizes, int n_in,
                              void* d_out, int out_size) {
    const float* x     = (const float*)d_in[0];   // (512, 13)
    const float* theta = (const float*)d_in[1];   // (130,)
    const float* bias  = (const float*)d_in[2];   // (1,)
    float* out = (float*)d_out;                   // (512, 2)

    const int SMEM = 65536 + 32768 + 1040 + 52 + 52 + 32 + 12; // ~99.5 KB
    cudaFuncSetAttribute(qubit_classifier_kernel,
                         cudaFuncAttributeMaxDynamicSharedMemorySize, SMEM);
    qubit_classifier_kernel<<<512, 256, SMEM>>>(x, theta, bias, out);
}

// round 16
// speedup vs baseline: 1.5674x; 1.5674x over previous
#include <cuda_runtime.h>

// QubitClassifier: 13-qubit ZZ-feature-map + variational circuit, B=512.
// One CTA per sample. State (8192 complex fp32) in shared memory.
// 512 threads x 16 amplitudes in registers; gates applied in 4-qubit
// register-blocked rounds (gates on distinct qubits commute).

#define PI_F 3.14159274101257324f

// XOR swizzle: bank-conflict-free SMEM access for all 4 maps, bijective on [0,8192).
__device__ __forceinline__ int swz(int i) { return i ^ ((i >> 4) & 15) ^ ((i >> 8) & 15); }

// Rz(b)Ry(a) gate: a0' = em*(ca*a0 - sa*a1), a1' = conj(em)*(sa*a0 + ca*a1)
// g = (ca, sa, em.x, em.y) with em = exp(-i b/2).
__device__ __forceinline__ void cgate(float2& a0, float2& a1, float4 g) {
    float ca = g.x, sa = g.y, ex = g.z, ey = g.w;
    float t0x = ca * a0.x - sa * a1.x;
    float t0y = ca * a0.y - sa * a1.y;
    float t1x = sa * a0.x + ca * a1.x;
    float t1y = sa * a0.y + ca * a1.y;
    a0.x = ex * t0x - ey * t0y;
    a0.y = ex * t0y + ey * t0x;
    a1.x = ex * t1x + ey * t1y;
    a1.y = ex * t1y - ey * t1x;
}

__device__ __forceinline__ void hpair(float2& a0, float2& a1) {
    float2 u = a0, v = a1;
    a0.x = u.x + v.x; a0.y = u.y + v.y;
    a1.x = u.x - v.x; a1.y = u.y - v.y;
}

// t: 9 bits (512 threads), m: 4 bits (16 amps).
// MAP0: reg bits -> global bits 0..3   (qubits 12..9)
// MAP1: reg bits -> global bits 4..7   (qubits 8..5)
// MAP2: reg bits -> global bits 8..11  (qubits 4..1)
// MAP3: reg bit 3 -> global bit 12 (qubit 0); bits 0..2 -> bits 9..11 (filler)
template <int MAP>
__device__ __forceinline__ int gidx(int t, int m) {
    if (MAP == 0) return (t << 4) | m;
    else if (MAP == 1) return ((t >> 4) << 8) | (m << 4) | (t & 15);
    else if (MAP == 2) return ((t >> 8) << 12) | (m << 8) | (t & 255);
    else return ((m >> 3) << 12) | ((m & 7) << 9) | t;
}

template <int MAP>
__device__ __forceinline__ void load_amp(const float2* S, float2 amp[16], int t, bool ent) {
#pragma unroll
    for (int m = 0; m < 16; m++) {
        int idx = gidx<MAP>(t, m);
        float2 a = S[swz(idx)];
        if (ent && (__popc(idx & (idx >> 1)) & 1)) { a.x = -a.x; a.y = -a.y; }
        amp[m] = a;
    }
}

template <int MAP>
__device__ __forceinline__ void store_amp(float2* S, const float2 amp[16], int t) {
#pragma unroll
    for (int m = 0; m < 16; m++) S[swz(gidx<MAP>(t, m))] = amp[m];
}

template <int MAP>
__device__ __forceinline__ void apply_gates(float2 amp[16], const float4* GP, int l) {
    const int k0 = (MAP == 3) ? 3 : 0;
#pragma unroll
    for (int k = k0; k < 4; k++) {
        int q = (MAP == 0) ? (12 - k) : ((MAP == 1) ? (8 - k) : ((MAP == 2) ? (4 - k) : 0));
        float4 g = GP[l * 13 + q];
#pragma unroll
        for (int j = 0; j < 16; j++)
            if (!((j >> k) & 1)) cgate(amp[j], amp[j | (1 << k)], g);
    }
}

template <int MAP>
__device__ __forceinline__ void apply_h(float2 amp[16]) {
    const int k0 = (MAP == 3) ? 3 : 0;
#pragma unroll
    for (int k = k0; k < 4; k++)
#pragma unroll
        for (int j = 0; j < 16; j++)
            if (!((j >> k) & 1)) hpair(amp[j], amp[j | (1 << k)]);
}

__global__ void __launch_bounds__(512, 1)
qubit_classifier_kernel(const float* __restrict__ x,
                        const float* __restrict__ theta,
                        const float* __restrict__ bias,
                        float* __restrict__ out)
{
    extern __shared__ char sm[];
    float2* S  = (float2*)sm;                               // 65536 B: state
    float*  F  = (float*)(sm + 65536);                      // 32768 B: phi(b)
    float4* GP = (float4*)(sm + 65536 + 32768);             //  1040 B: 65 gates
    float*  XS = (float*)(sm + 65536 + 32768 + 1040);       //    52 B
    float*  AS = XS + 13;                                   //    52 B
    float*  RED = AS + 13;                                  //    64 B

    const int t = threadIdx.x;
    const int b = blockIdx.x;

    if (t < 65) {
        float tha = theta[2 * t], thb = theta[2 * t + 1];
        float sa, ca; sincosf(0.5f * tha, &sa, &ca);
        float sb, cb; sincosf(0.5f * thb, &sb, &cb);
        GP[t] = make_float4(ca, sa, cb, -sb);   // em = exp(-i thb/2)
    }
    if (t < 13) {
        float xv = x[b * 13 + t];
        XS[t] = xv;
        AS[t] = PI_F - xv;
    }
    __syncthreads();

    float Asum = 0.f;
#pragma unroll
    for (int q = 0; q < 13; q++) { float a = AS[q]; Asum += a * a; }

    // phi = u + 0.5*(v^2 - Asum): hi part from thread bits (global bits 4..12),
    // lo part from register bits (global bits 0..3). Global bit p <-> qubit 12-p.
    float uhi = 0.f, vhi = 0.f;
#pragma unroll
    for (int p = 4; p < 13; p++) {
        int bit = (t >> (p - 4)) & 1;
        float xv = XS[12 - p], av = AS[12 - p];
        uhi += bit ? -xv : xv;
        vhi += bit ? -av : av;
    }
    float xlo[4], alo[4];
#pragma unroll
    for (int k = 0; k < 4; k++) { xlo[k] = XS[12 - k]; alo[k] = AS[12 - k]; }

    float2 amp[16];

    // ---- Pass 1 (MAP0): init amp = exp(i*phi)/8192 (both norms folded),
    //      store phi, H on qubits 12..9. ----
#pragma unroll
    for (int m = 0; m < 16; m++) {
        float u = uhi, v = vhi;
#pragma unroll
        for (int k = 0; k < 4; k++) {
            int bit = (m >> k) & 1;
            u += bit ? -xlo[k] : xlo[k];
            v += bit ? -alo[k] : alo[k];
        }
        float phi = u + 0.5f * (v * v - Asum);
        int idx = (t << 4) | m;
        F[swz(idx)] = phi;
        float sn, cs; sincosf(phi, &sn, &cs);
        const float c = 1.0f / 8192.0f;   // 2^{-13/2} init * 2^{-13/2} FWHT norm
        amp[m] = make_float2(cs * c, sn * c);
    }
    apply_h<0>(amp);
    store_amp<0>(S, amp, t);
    __syncthreads();

    // ---- Pass 2 (MAP1): H on qubits 8..5 ----
    load_amp<1>(S, amp, t, false);
    apply_h<1>(amp);
    store_amp<1>(S, amp, t);
    __syncthreads();

    // ---- Pass 3 (MAP2): H on qubits 4..1 ----
    load_amp<2>(S, amp, t, false);
    apply_h<2>(amp);
    store_amp<2>(S, amp, t);
    __syncthreads();

    // ---- Pass 4 (MAP3): H on qubit 0, second d = exp(i*phi), layer-0 gate q0 ----
    load_amp<3>(S, amp, t, false);
    apply_h<3>(amp);
#pragma unroll
    for (int m = 0; m < 16; m++) {
        int idx = gidx<3>(t, m);
        float phi = F[swz(idx)];
        float sn, cs; sincosf(phi, &sn, &cs);
        float2 a = amp[m];
        amp[m] = make_float2(a.x * cs - a.y * sn, a.x * sn + a.y * cs);
    }
    apply_gates<3>(amp, GP, 0);
    store_amp<3>(S, amp, t);
    __syncthreads();

    // ---- Passes 5-7: remaining layer-0 gates ----
    load_amp<0>(S, amp, t, false);
    apply_gates<0>(amp, GP, 0);
    store_amp<0>(S, amp, t);
    __syncthreads();

    load_amp<1>(S, amp, t, false);
    apply_gates<1>(amp, GP, 0);
    store_amp<1>(S, amp, t);
    __syncthreads();

    load_amp<2>(S, amp, t, false);
    apply_gates<2>(amp, GP, 0);
    store_amp<2>(S, amp, t);
    __syncthreads();

    // ---- Layers 1..4: ENT fused into first load; layer-4's last pass (MAP3)
    //      fuses the parity-weighted probability reduction (no store). ----
    float acc = 0.f;
#pragma unroll 1
    for (int l = 1; l < 5; l++) {
        load_amp<0>(S, amp, t, true);          // * ENT = (-1)^popc(b & (b>>1))
        apply_gates<0>(amp, GP, l);
        store_amp<0>(S, amp, t);
        __syncthreads();

        load_amp<1>(S, amp, t, false);
        apply_gates<1>(amp, GP, l);
        store_amp<1>(S, amp, t);
        __syncthreads();

        load_amp<2>(S, amp, t, false);
        apply_gates<2>(amp, GP, l);
        store_amp<2>(S, amp, t);
        __syncthreads();

        load_amp<3>(S, amp, t, false);
        apply_gates<3>(amp, GP, l);
        if (l < 4) {
            store_amp<3>(S, amp, t);
            __syncthreads();
        } else {
#pragma unroll
            for (int m = 0; m < 16; m++) {
                int idx = gidx<3>(t, m);
                float p = amp[m].x * amp[m].x + amp[m].y * amp[m].y;
                acc += (__popc(idx) & 1) ? -p : p;
            }
        }
    }

    // Block reduction
#pragma unroll
    for (int off = 16; off; off >>= 1)
        acc += __shfl_xor_sync(0xffffffffu, acc, off);
    if ((t & 31) == 0) RED[t >> 5] = acc;
    __syncthreads();
    if (t == 0) {
        float s = 0.f;
#pragma unroll
        for (int w = 0; w < 16; w++) s += RED[w];
        float logit = s + bias[0];
        out[2 * b + 0] = -logit;
        out[2 * b + 1] = logit;
    }
}

extern "C" void kernel_launch(void* const* d_in, const int* in_sizes, int n_in,
                              void* d_out, int out_size) {
    const float* x     = (const float*)d_in[0];   // (512, 13)
    const float* theta = (const float*)d_in[1];   // (130,)
    const float* bias  = (const float*)d_in[2];   // (1,)
    float* out = (float*)d_out;                   // (512, 2)

    const int SMEM = 65536 + 32768 + 1040 + 52 + 52 + 64 + 16; // ~99.5 KB
    cudaFuncSetAttribute(qubit_classifier_kernel,
                         cudaFuncAttributeMaxDynamicSharedMemorySize, SMEM);
    qubit_classifier_kernel<<<512, 512, SMEM>>>(x, theta, bias, out);
}

// round 17
// speedup vs baseline: 1.5992x; 1.0203x over previous
#include <cuda_runtime.h>

// QubitClassifier: 13-qubit ZZ-feature-map + variational circuit, B=512.
// One CTA per sample. State (8192 complex fp32) in shared memory.
// 1024 threads x 8 amplitudes in registers (<=64 regs/thread -> 32 warps/SM);
// gates applied in 3-qubit register-blocked rounds (gates on distinct
// qubits commute).

#define PI_F 3.14159274101257324f

// GF(2)-linear swizzle: bank-conflict-free for all 5 maps (verified by rank
// analysis per 16-lane LDS.64 phase, and full-warp for the 4B phi array).
__device__ __forceinline__ int swz(int i) {
    return i ^ ((i >> 3) & 30) ^ ((i >> 6) & 1);
}

// Rz(b)Ry(a) gate: a0' = em*(ca*a0 - sa*a1), a1' = conj(em)*(sa*a0 + ca*a1)
// g = (ca, sa, em.x, em.y) with em = exp(-i b/2).
__device__ __forceinline__ void cgate(float2& a0, float2& a1, float4 g) {
    float ca = g.x, sa = g.y, ex = g.z, ey = g.w;
    float t0x = ca * a0.x - sa * a1.x;
    float t0y = ca * a0.y - sa * a1.y;
    float t1x = sa * a0.x + ca * a1.x;
    float t1y = sa * a0.y + ca * a1.y;
    a0.x = ex * t0x - ey * t0y;
    a0.y = ex * t0y + ey * t0x;
    a1.x = ex * t1x + ey * t1y;
    a1.y = ex * t1y - ey * t1x;
}

__device__ __forceinline__ void hpair(float2& a0, float2& a1) {
    float2 u = a0, v = a1;
    a0.x = u.x + v.x; a0.y = u.y + v.y;
    a1.x = u.x - v.x; a1.y = u.y - v.y;
}

// t: 10 bits (1024 threads), m: 3 bits (8 amps). idx bit p <-> qubit 12-p.
// MAP0: m -> idx bits 0..2   (qubits 12..10)
// MAP1: m -> idx bits 3..5   (qubits 9..7)
// MAP2: m -> idx bits 6..8   (qubits 6..4)
// MAP3: m -> idx bits 9..11  (qubits 3..1)
// MAP4: m bit2 -> idx bit 12 (qubit 0); m bits 0..1 -> bits 10..11 (filler)
template <int MAP>
__device__ __forceinline__ int gidx(int t, int m) {
    if (MAP == 0) return (t << 3) | m;
    else if (MAP == 1) return ((t >> 3) << 6) | (m << 3) | (t & 7);
    else if (MAP == 2) return ((t >> 6) << 9) | (m << 6) | (t & 63);
    else if (MAP == 3) return ((t >> 9) << 12) | (m << 9) | (t & 511);
    else return ((m >> 2) << 12) | ((m & 3) << 10) | t;
}

template <int MAP>
__device__ __forceinline__ void load_amp(const float2* S, float2 amp[8], int t, bool ent) {
#pragma unroll
    for (int m = 0; m < 8; m++) {
        int idx = gidx<MAP>(t, m);
        float2 a = S[swz(idx)];
        if (ent && (__popc(idx & (idx >> 1)) & 1)) { a.x = -a.x; a.y = -a.y; }
        amp[m] = a;
    }
}

template <int MAP>
__device__ __forceinline__ void store_amp(float2* S, const float2 amp[8], int t) {
#pragma unroll
    for (int m = 0; m < 8; m++) S[swz(gidx<MAP>(t, m))] = amp[m];
}

template <int MAP>
__device__ __forceinline__ void apply_gates(float2 amp[8], const float4* GP, int l) {
    const int k0 = (MAP == 4) ? 2 : 0;
#pragma unroll
    for (int k = k0; k < 3; k++) {
        int q = (MAP == 0) ? (12 - k) : (MAP == 1) ? (9 - k)
              : (MAP == 2) ? (6 - k)  : (MAP == 3) ? (3 - k) : 0;
        float4 g = GP[l * 13 + q];
#pragma unroll
        for (int j = 0; j < 8; j++)
            if (!((j >> k) & 1)) cgate(amp[j], amp[j | (1 << k)], g);
    }
}

template <int MAP>
__device__ __forceinline__ void apply_h(float2 amp[8]) {
    const int k0 = (MAP == 4) ? 2 : 0;
#pragma unroll
    for (int k = k0; k < 3; k++)
#pragma unroll
        for (int j = 0; j < 8; j++)
            if (!((j >> k) & 1)) hpair(amp[j], amp[j | (1 << k)]);
}

__global__ void __launch_bounds__(1024, 1)
qubit_classifier_kernel(const float* __restrict__ x,
                        const float* __restrict__ theta,
                        const float* __restrict__ bias,
                        float* __restrict__ out)
{
    extern __shared__ char sm[];
    float2* S  = (float2*)sm;                               // 65536 B: state
    float*  F  = (float*)(sm + 65536);                      // 32768 B: phi(b)
    float4* GP = (float4*)(sm + 65536 + 32768);             //  1040 B: 65 gates
    float*  XS = (float*)(sm + 65536 + 32768 + 1040);       //    52 B
    float*  AS = XS + 13;                                   //    52 B
    float*  RED = AS + 13;                                  //   128 B

    const int t = threadIdx.x;
    const int b = blockIdx.x;

    if (t < 65) {
        float tha = theta[2 * t], thb = theta[2 * t + 1];
        float sa, ca; sincosf(0.5f * tha, &sa, &ca);
        float sb, cb; sincosf(0.5f * thb, &sb, &cb);
        GP[t] = make_float4(ca, sa, cb, -sb);   // em = exp(-i thb/2)
    }
    if (t < 13) {
        float xv = x[b * 13 + t];
        XS[t] = xv;
        AS[t] = PI_F - xv;
    }
    __syncthreads();

    float Asum = 0.f;
#pragma unroll
    for (int q = 0; q < 13; q++) { float a = AS[q]; Asum += a * a; }

    // phi = u + 0.5*(v^2 - Asum). Pass-1 layout (MAP0): idx = (t<<3)|m,
    // idx bit p <-> qubit 12-p. hi from t (idx bits 3..12), lo from m (bits 0..2).
    float uhi = 0.f, vhi = 0.f;
#pragma unroll
    for (int p = 3; p < 13; p++) {
        int bit = (t >> (p - 3)) & 1;
        float xv = XS[12 - p], av = AS[12 - p];
        uhi += bit ? -xv : xv;
        vhi += bit ? -av : av;
    }
    float xlo[3], alo[3];
#pragma unroll
    for (int k = 0; k < 3; k++) { xlo[k] = XS[12 - k]; alo[k] = AS[12 - k]; }

    float2 amp[8];

    // ---- Pass 1 (MAP0): init amp = exp(i*phi)/8192 (both norms folded),
    //      store phi, H on qubits 12..10 ----
#pragma unroll
    for (int m = 0; m < 8; m++) {
        float u = uhi, v = vhi;
#pragma unroll
        for (int k = 0; k < 3; k++) {
            int bit = (m >> k) & 1;
            u += bit ? -xlo[k] : xlo[k];
            v += bit ? -alo[k] : alo[k];
        }
        float phi = u + 0.5f * (v * v - Asum);
        int idx = (t << 3) | m;
        F[swz(idx)] = phi;
        float sn, cs; sincosf(phi, &sn, &cs);
        const float c = 1.0f / 8192.0f;   // 2^{-13/2} init * 2^{-13/2} FWHT norm
        amp[m] = make_float2(cs * c, sn * c);
    }
    apply_h<0>(amp);
    store_amp<0>(S, amp, t);
    __syncthreads();

    // ---- Passes 2-4: H on qubits 9..7, 6..4, 3..1 ----
    load_amp<1>(S, amp, t, false);
    apply_h<1>(amp);
    store_amp<1>(S, amp, t);
    __syncthreads();

    load_amp<2>(S, amp, t, false);
    apply_h<2>(amp);
    store_amp<2>(S, amp, t);
    __syncthreads();

    load_amp<3>(S, amp, t, false);
    apply_h<3>(amp);
    store_amp<3>(S, amp, t);
    __syncthreads();

    // ---- Pass 5 (MAP4): H on qubit 0, second d = exp(i*phi), layer-0 gate q0 ----
    load_amp<4>(S, amp, t, false);
    apply_h<4>(amp);
#pragma unroll
    for (int m = 0; m < 8; m++) {
        int idx = gidx<4>(t, m);
        float phi = F[swz(idx)];
        float sn, cs; sincosf(phi, &sn, &cs);
        float2 a = amp[m];
        amp[m] = make_float2(a.x * cs - a.y * sn, a.x * sn + a.y * cs);
    }
    apply_gates<4>(amp, GP, 0);
    store_amp<4>(S, amp, t);
    __syncthreads();

    // ---- Passes 6-9: remaining layer-0 gates ----
    load_amp<0>(S, amp, t, false);
    apply_gates<0>(amp, GP, 0);
    store_amp<0>(S, amp, t);
    __syncthreads();

    load_amp<1>(S, amp, t, false);
    apply_gates<1>(amp, GP, 0);
    store_amp<1>(S, amp, t);
    __syncthreads();

    load_amp<2>(S, amp, t, false);
    apply_gates<2>(amp, GP, 0);
    store_amp<2>(S, amp, t);
    __syncthreads();

    load_amp<3>(S, amp, t, false);
    apply_gates<3>(amp, GP, 0);
    store_amp<3>(S, amp, t);
    __syncthreads();

    // ---- Layers 1..4: ENT fused into first load; layer-4's last pass (MAP4)
    //      fuses the parity-weighted probability reduction (no store). ----
    float acc = 0.f;
#pragma unroll 1
    for (int l = 1; l < 5; l++) {
        load_amp<0>(S, amp, t, true);          // * ENT = (-1)^popc(b & (b>>1))
        apply_gates<0>(amp, GP, l);
        store_amp<0>(S, amp, t);
        __syncthreads();

        load_amp<1>(S, amp, t, false);
        apply_gates<1>(amp, GP, l);
        store_amp<1>(S, amp, t);
        __syncthreads();

        load_amp<2>(S, amp, t, false);
        apply_gates<2>(amp, GP, l);
        store_amp<2>(S, amp, t);
        __syncthreads();

        load_amp<3>(S, amp, t, false);
        apply_gates<3>(amp, GP, l);
        store_amp<3>(S, amp, t);
        __syncthreads();

        load_amp<4>(S, amp, t, false);
        apply_gates<4>(amp, GP, l);
        if (l < 4) {
            store_amp<4>(S, amp, t);
            __syncthreads();
        } else {
#pragma unroll
            for (int m = 0; m < 8; m++) {
                int idx = gidx<4>(t, m);
                float p = amp[m].x * amp[m].x + amp[m].y * amp[m].y;
                acc += (__popc(idx) & 1) ? -p : p;
            }
        }
    }

    // Block reduction
#pragma unroll
    for (int off = 16; off; off >>= 1)
        acc += __shfl_xor_sync(0xffffffffu, acc, off);
    if ((t & 31) == 0) RED[t >> 5] = acc;
    __syncthreads();
    if (t == 0) {
        float s = 0.f;
#pragma unroll
        for (int w = 0; w < 32; w++) s += RED[w];
        float logit = s + bias[0];
        out[2 * b + 0] = -logit;
        out[2 * b + 1] = logit;
    }
}

extern "C" void kernel_launch(void* const* d_in, const int* in_sizes, int n_in,
                              void* d_out, int out_size) {
    const float* x     = (const float*)d_in[0];   // (512, 13)
    const float* theta = (const float*)d_in[1];   // (130,)
    const float* bias  = (const float*)d_in[2];   // (1,)
    float* out = (float*)d_out;                   // (512, 2)

    const int SMEM = 65536 + 32768 + 1040 + 52 + 52 + 128 + 16; // ~99.6 KB
    cudaFuncSetAttribute(qubit_classifier_kernel,
                         cudaFuncAttributeMaxDynamicSharedMemorySize, SMEM);
    qubit_classifier_kernel<<<512, 1024, SMEM>>>(x, theta, bias, out);
}